// round 1
// baseline (speedup 1.0000x reference)
#include <cuda_runtime.h>
#include <math.h>

#define B_  4
#define N_  2048
#define D_  1024
#define E_  8
#define H_  4096
#define C_  320
#define BN_TOK (B_*N_)

// -------- scratch (device globals: allocation-free) --------
__device__ float g_Y[(size_t)B_*E_*C_*H_];   // expert hidden activations, ~168 MB
__device__ int   g_s2t[B_*E_*C_];            // slot -> token (or -1)
__device__ int   g_cnt[B_*E_];               // raw routed counts (pre-capacity)
__device__ float g_proxy[B_*E_];             // sum of router probs per (b,e)
__device__ float g_gate[BN_TOK];
__device__ int   g_idx[BN_TOK];
__device__ float g_z2;

// ---------------- init ----------------
__global__ void k_init() {
    int i = blockIdx.x * blockDim.x + threadIdx.x;
    if (i < B_*E_*C_) g_s2t[i] = -1;
    if (i < B_*E_)    g_proxy[i] = 0.f;
    if (i == 0)       g_z2 = 0.f;
}

// ---------------- router ----------------
// one block (128 thr) per token: logits[8], softmax, argmax, gate, z
__global__ void k_router(const float* __restrict__ x, const float* __restrict__ wr) {
    int t = blockIdx.x;                 // token in [0, B*N)
    int b = t / N_;
    const float* xr = x + (size_t)t * D_;
    float acc[E_];
#pragma unroll
    for (int e = 0; e < E_; e++) acc[e] = 0.f;

    for (int d = threadIdx.x; d < D_; d += blockDim.x) {
        float xv = __ldg(xr + d);
        const float4* w4 = (const float4*)(wr + (size_t)d * E_);
        float4 w0 = w4[0], w1 = w4[1];
        acc[0] += xv * w0.x; acc[1] += xv * w0.y;
        acc[2] += xv * w0.z; acc[3] += xv * w0.w;
        acc[4] += xv * w1.x; acc[5] += xv * w1.y;
        acc[6] += xv * w1.z; acc[7] += xv * w1.w;
    }

    __shared__ float sh[4][E_];
    int lane = threadIdx.x & 31, warp = threadIdx.x >> 5;
#pragma unroll
    for (int e = 0; e < E_; e++) {
        float v = acc[e];
#pragma unroll
        for (int off = 16; off > 0; off >>= 1) v += __shfl_down_sync(0xffffffffu, v, off);
        if (lane == 0) sh[warp][e] = v;
    }
    __syncthreads();

    if (threadIdx.x == 0) {
        float logits[E_];
#pragma unroll
        for (int e = 0; e < E_; e++) logits[e] = sh[0][e] + sh[1][e] + sh[2][e] + sh[3][e];
        float maxl = logits[0]; int amax = 0;
#pragma unroll
        for (int e = 1; e < E_; e++) if (logits[e] > maxl) { maxl = logits[e]; amax = e; }
        float sum = 0.f, p[E_];
#pragma unroll
        for (int e = 0; e < E_; e++) { p[e] = expf(logits[e] - maxl); sum += p[e]; }
        float inv = 1.f / sum;
        float z = maxl + logf(sum);
#pragma unroll
        for (int e = 0; e < E_; e++) atomicAdd(&g_proxy[b*E_ + e], p[e] * inv);
        atomicAdd(&g_z2, z * z);
        g_idx[t]  = amax;
        g_gate[t] = p[amax] * inv;
    }
}

// ---------------- capacity scan ----------------
// one warp per (b,e): ballot-based prefix over N tokens
__global__ void k_scan() {
    int be = blockIdx.x;
    int b = be / E_, e = be % E_;
    int lane = threadIdx.x;
    unsigned lt = (1u << lane) - 1u;
    int base = 0;
    for (int n0 = 0; n0 < N_; n0 += 32) {
        int n = n0 + lane;
        int pred = (g_idx[b*N_ + n] == e);
        unsigned bal = __ballot_sync(0xffffffffu, pred);
        if (pred) {
            int slot = base + __popc(bal & lt);
            if (slot < C_) g_s2t[be*C_ + slot] = n;
        }
        base += __popc(bal);
    }
    if (lane == 0) g_cnt[be] = base;
}

// ---------------- scalar losses ----------------
__global__ void k_final(float* __restrict__ out) {
    float aux = 0.f;
    for (int be = 0; be < B_*E_; be++)
        aux += ((float)g_cnt[be] / (float)N_) * (g_proxy[be] / (float)N_);
    aux *= (float)(E_*E_) / (float)B_;
    out[(size_t)BN_TOK * D_]     = aux;
    out[(size_t)BN_TOK * D_ + 1] = g_z2 / (float)BN_TOK;
}

// ---------------- GELU (tanh approx, matches jax.nn.gelu default) ----------------
__device__ __forceinline__ float gelu_tanh(float v) {
    float v3 = v * v * v;
    return 0.5f * v * (1.f + tanhf(0.7978845608028654f * (v + 0.044715f * v3)));
}

// ---------------- GEMM1: Y[be] = gelu(gather(x)[C,D] @ w1[e][D,H] + b1[e]) ----------------
// tiles: BM=BN=64, BK=16; 256 threads; 4x4 per thread
__global__ void __launch_bounds__(256, 4) k_gemm1(const float* __restrict__ x,
                                                  const float* __restrict__ w1,
                                                  const float* __restrict__ b1) {
    constexpr int BM = 64, BN = 64, BK = 16;
    __shared__ __align__(16) float As[BK][BM];
    __shared__ __align__(16) float Bs[BK][BN];
    __shared__ int tok[BM];

    int be = blockIdx.z, b = be >> 3, e = be & 7;
    int m0 = blockIdx.y * BM, n0 = blockIdx.x * BN;
    int tid = threadIdx.x;

    if (tid < BM) tok[tid] = g_s2t[be*C_ + m0 + tid];
    __syncthreads();

    int arow = tid >> 2, acol = (tid & 3) * 4;    // A tile: 64 rows x 16 cols
    int brow = tid >> 4, bcol = (tid & 15) * 4;   // B tile: 16 rows x 64 cols
    int tm0 = (tid >> 4) * 4, tn0 = (tid & 15) * 4;

    const float* wB = w1 + (size_t)e * D_ * H_;
    int atok = tok[arow];
    const float* aptr = (atok >= 0) ? (x + ((size_t)(b*N_ + atok)) * D_ + acol) : nullptr;

    float acc[4][4];
#pragma unroll
    for (int i = 0; i < 4; i++)
#pragma unroll
        for (int j = 0; j < 4; j++) acc[i][j] = 0.f;

    for (int k0 = 0; k0 < D_; k0 += BK) {
        float4 av = make_float4(0.f, 0.f, 0.f, 0.f);
        if (aptr) av = *(const float4*)(aptr + k0);
        As[acol+0][arow] = av.x; As[acol+1][arow] = av.y;
        As[acol+2][arow] = av.z; As[acol+3][arow] = av.w;
        *(float4*)&Bs[brow][bcol] =
            *(const float4*)(wB + (size_t)(k0 + brow) * H_ + n0 + bcol);
        __syncthreads();
#pragma unroll
        for (int k = 0; k < BK; k++) {
            float rm[4], rn[4];
            *(float4*)rm = *(const float4*)&As[k][tm0];
            *(float4*)rn = *(const float4*)&Bs[k][tn0];
#pragma unroll
            for (int i = 0; i < 4; i++)
#pragma unroll
                for (int j = 0; j < 4; j++) acc[i][j] += rm[i] * rn[j];
        }
        __syncthreads();
    }

    float* Yout = g_Y + ((size_t)be * C_ + m0 + tm0) * H_ + n0 + tn0;
    const float* bb = b1 + (size_t)e * H_ + n0 + tn0;
#pragma unroll
    for (int i = 0; i < 4; i++) {
        float4 v;
        v.x = gelu_tanh(acc[i][0] + bb[0]);
        v.y = gelu_tanh(acc[i][1] + bb[1]);
        v.z = gelu_tanh(acc[i][2] + bb[2]);
        v.w = gelu_tanh(acc[i][3] + bb[3]);
        *(float4*)(Yout + (size_t)i * H_) = v;
    }
}

// ---------------- GEMM2 + scatter: out[tok] = gate * (Y[be] @ w2[e] + b2[e]) ----------------
__global__ void __launch_bounds__(256, 4) k_gemm2(const float* __restrict__ w2,
                                                  const float* __restrict__ b2,
                                                  float* __restrict__ out) {
    constexpr int BM = 64, BN = 64, BK = 16;
    __shared__ __align__(16) float As[BK][BM];
    __shared__ __align__(16) float Bs[BK][BN];
    __shared__ int tok[BM];

    int be = blockIdx.z, b = be >> 3, e = be & 7;
    int m0 = blockIdx.y * BM, n0 = blockIdx.x * BN;
    int tid = threadIdx.x;

    if (tid < BM) tok[tid] = g_s2t[be*C_ + m0 + tid];
    __syncthreads();

    int arow = tid >> 2, acol = (tid & 3) * 4;
    int brow = tid >> 4, bcol = (tid & 15) * 4;
    int tm0 = (tid >> 4) * 4, tn0 = (tid & 15) * 4;

    const float* Ain = g_Y + ((size_t)be * C_ + m0 + arow) * H_ + acol;
    const float* wB  = w2 + (size_t)e * H_ * D_;

    float acc[4][4];
#pragma unroll
    for (int i = 0; i < 4; i++)
#pragma unroll
        for (int j = 0; j < 4; j++) acc[i][j] = 0.f;

    for (int k0 = 0; k0 < H_; k0 += BK) {
        float4 av = *(const float4*)(Ain + k0);
        As[acol+0][arow] = av.x; As[acol+1][arow] = av.y;
        As[acol+2][arow] = av.z; As[acol+3][arow] = av.w;
        *(float4*)&Bs[brow][bcol] =
            *(const float4*)(wB + (size_t)(k0 + brow) * D_ + n0 + bcol);
        __syncthreads();
#pragma unroll
        for (int k = 0; k < BK; k++) {
            float rm[4], rn[4];
            *(float4*)rm = *(const float4*)&As[k][tm0];
            *(float4*)rn = *(const float4*)&Bs[k][tn0];
#pragma unroll
            for (int i = 0; i < 4; i++)
#pragma unroll
                for (int j = 0; j < 4; j++) acc[i][j] += rm[i] * rn[j];
        }
        __syncthreads();
    }

    const float* bb = b2 + (size_t)e * D_ + n0 + tn0;
#pragma unroll
    for (int i = 0; i < 4; i++) {
        int tk = tok[tm0 + i];
        if (tk >= 0) {
            float gate = g_gate[b*N_ + tk];
            float4 v;
            v.x = gate * (acc[i][0] + bb[0]);
            v.y = gate * (acc[i][1] + bb[1]);
            v.z = gate * (acc[i][2] + bb[2]);
            v.w = gate * (acc[i][3] + bb[3]);
            *(float4*)(out + ((size_t)(b*N_ + tk)) * D_ + n0 + tn0) = v;
        }
    }
}

// ---------------- launch ----------------
extern "C" void kernel_launch(void* const* d_in, const int* in_sizes, int n_in,
                              void* d_out, int out_size) {
    const float* x  = (const float*)d_in[0];
    const float* wr = (const float*)d_in[1];
    const float* w1 = (const float*)d_in[2];
    const float* b1 = (const float*)d_in[3];
    const float* w2 = (const float*)d_in[4];
    const float* b2 = (const float*)d_in[5];
    float* out = (float*)d_out;

    cudaMemsetAsync(out, 0, (size_t)out_size * sizeof(float), 0);
    k_init<<<(B_*E_*C_ + 255) / 256, 256>>>();
    k_router<<<BN_TOK, 128>>>(x, wr);
    k_scan<<<B_*E_, 32>>>();
    k_final<<<1, 1>>>(out);
    k_gemm1<<<dim3(H_/64, C_/64, B_*E_), 256>>>(x, w1, b1);
    k_gemm2<<<dim3(D_/64, C_/64, B_*E_), 256>>>(w2, b2, out);
}

// round 2
// speedup vs baseline: 3.3211x; 3.3211x over previous
#include <cuda_runtime.h>
#include <math.h>

#define B_  4
#define N_  2048
#define D_  1024
#define E_  8
#define H_  4096
#define C_  320
#define BN_TOK (B_*N_)

// -------- scratch (device globals: allocation-free) --------
__device__ float g_Y[(size_t)B_*E_*C_*H_];   // expert hidden (tf32-rounded fp32)
__device__ float g_xt[(size_t)BN_TOK*D_];    // x pre-rounded to tf32
__device__ int   g_s2t[B_*E_*C_];            // slot -> token (or -1)
__device__ int   g_cnt[B_*E_];
__device__ float g_proxy[B_*E_];
__device__ float g_gate[BN_TOK];
__device__ int   g_idx[BN_TOK];
__device__ float g_z2;

// ---------------- helpers ----------------
__device__ __forceinline__ unsigned f2tf32(float f) {
    unsigned u; asm("cvt.rna.tf32.f32 %0, %1;" : "=r"(u) : "f"(f)); return u;
}
__device__ __forceinline__ void mma8(float c[4], const unsigned a[4], const unsigned b[2]) {
    asm volatile("mma.sync.aligned.m16n8k8.row.col.f32.tf32.tf32.f32 "
                 "{%0,%1,%2,%3},{%4,%5,%6,%7},{%8,%9},{%0,%1,%2,%3};"
                 : "+f"(c[0]), "+f"(c[1]), "+f"(c[2]), "+f"(c[3])
                 : "r"(a[0]), "r"(a[1]), "r"(a[2]), "r"(a[3]), "r"(b[0]), "r"(b[1]));
}
__device__ __forceinline__ void cp16(unsigned saddr, const void* g, int sz) {
    asm volatile("cp.async.cg.shared.global [%0], [%1], 16, %2;"
                 :: "r"(saddr), "l"(g), "r"(sz));
}
__device__ __forceinline__ void cpcommit() { asm volatile("cp.async.commit_group;"); }
template<int n> __device__ __forceinline__ void cpwait() {
    asm volatile("cp.async.wait_group %0;" :: "n"(n));
}
__device__ __forceinline__ float gelu_tanh(float v) {
    float v3 = v * v * v;
    return 0.5f * v * (1.f + tanhf(0.7978845608028654f * (v + 0.044715f * v3)));
}

// ---------------- init ----------------
__global__ void k_init() {
    int i = blockIdx.x * blockDim.x + threadIdx.x;
    if (i < B_*E_*C_) g_s2t[i] = -1;
    if (i < B_*E_)    g_proxy[i] = 0.f;
    if (i == 0)       g_z2 = 0.f;
}

// ---------------- x -> tf32 pre-round ----------------
__global__ void k_cvtx(const float* __restrict__ x) {
    size_t i = (size_t)blockIdx.x * blockDim.x + threadIdx.x;
    float4 v = ((const float4*)x)[i];
    v.x = __uint_as_float(f2tf32(v.x));
    v.y = __uint_as_float(f2tf32(v.y));
    v.z = __uint_as_float(f2tf32(v.z));
    v.w = __uint_as_float(f2tf32(v.w));
    ((float4*)g_xt)[i] = v;
}

// ---------------- router ----------------
__global__ void k_router(const float* __restrict__ x, const float* __restrict__ wr) {
    int t = blockIdx.x;
    int b = t / N_;
    const float* xr = x + (size_t)t * D_;
    float acc[E_];
#pragma unroll
    for (int e = 0; e < E_; e++) acc[e] = 0.f;
    for (int d = threadIdx.x; d < D_; d += blockDim.x) {
        float xv = __ldg(xr + d);
        const float4* w4 = (const float4*)(wr + (size_t)d * E_);
        float4 w0 = w4[0], w1 = w4[1];
        acc[0] += xv * w0.x; acc[1] += xv * w0.y;
        acc[2] += xv * w0.z; acc[3] += xv * w0.w;
        acc[4] += xv * w1.x; acc[5] += xv * w1.y;
        acc[6] += xv * w1.z; acc[7] += xv * w1.w;
    }
    __shared__ float sh[4][E_];
    int lane = threadIdx.x & 31, warp = threadIdx.x >> 5;
#pragma unroll
    for (int e = 0; e < E_; e++) {
        float v = acc[e];
#pragma unroll
        for (int off = 16; off > 0; off >>= 1) v += __shfl_down_sync(0xffffffffu, v, off);
        if (lane == 0) sh[warp][e] = v;
    }
    __syncthreads();
    if (threadIdx.x == 0) {
        float logits[E_];
#pragma unroll
        for (int e = 0; e < E_; e++) logits[e] = sh[0][e] + sh[1][e] + sh[2][e] + sh[3][e];
        float maxl = logits[0]; int amax = 0;
#pragma unroll
        for (int e = 1; e < E_; e++) if (logits[e] > maxl) { maxl = logits[e]; amax = e; }
        float sum = 0.f, p[E_];
#pragma unroll
        for (int e = 0; e < E_; e++) { p[e] = expf(logits[e] - maxl); sum += p[e]; }
        float inv = 1.f / sum;
        float z = maxl + logf(sum);
#pragma unroll
        for (int e = 0; e < E_; e++) atomicAdd(&g_proxy[b*E_ + e], p[e] * inv);
        atomicAdd(&g_z2, z * z);
        g_idx[t]  = amax;
        g_gate[t] = p[amax] * inv;
    }
}

// ---------------- capacity scan ----------------
__global__ void k_scan() {
    int be = blockIdx.x;
    int b = be / E_, e = be % E_;
    int lane = threadIdx.x;
    unsigned lt = (1u << lane) - 1u;
    int base = 0;
    for (int n0 = 0; n0 < N_; n0 += 32) {
        int n = n0 + lane;
        int pred = (g_idx[b*N_ + n] == e);
        unsigned bal = __ballot_sync(0xffffffffu, pred);
        if (pred) {
            int slot = base + __popc(bal & lt);
            if (slot < C_) g_s2t[be*C_ + slot] = n;
        }
        base += __popc(bal);
    }
    if (lane == 0) g_cnt[be] = base;
}

// ---------------- scalar losses ----------------
__global__ void k_final(float* __restrict__ out) {
    float aux = 0.f;
    for (int be = 0; be < B_*E_; be++)
        aux += ((float)g_cnt[be] / (float)N_) * (g_proxy[be] / (float)N_);
    aux *= (float)(E_*E_) / (float)B_;
    out[(size_t)BN_TOK * D_]     = aux;
    out[(size_t)BN_TOK * D_ + 1] = g_z2 / (float)BN_TOK;
}

// ---------------- tf32 mma GEMM: BM=128 BN=128 BK=16, 8 warps (2x4), warp 64x32 ----------------
// IS_G1: A = gather(g_xt) [C,D], B = w1[e] [D,H]; out: g_Y = tf32(gelu(acc + b1))
// !IS_G1: A = g_Y [C,H], B = w2[e] [H,D]; out: scatter gate*(acc + b2) to out
template<bool IS_G1>
__global__ void __launch_bounds__(256, 2) k_mma(const float* __restrict__ Wg,
                                                const float* __restrict__ bias,
                                                float* __restrict__ outp)
{
    constexpr int LDB  = IS_G1 ? H_ : D_;    // B row stride / N extent
    constexpr int KDIM = IS_G1 ? D_ : H_;
    constexpr int ITERS = KDIM / 16;

    __shared__ float As[2][128][20];    // [k-stage][m][k] pad->conflict-free frags
    __shared__ float Bs[2][16][136];    // [stage][k][n] pad 8 -> conflict-free frags
    __shared__ int   tok[128];

    int be = blockIdx.z, b = be >> 3, e = be & 7;
    int m0 = blockIdx.y * 128, n0 = blockIdx.x * 128;
    int tid = threadIdx.x, lane = tid & 31, wid = tid >> 5;

    if (tid < 128) { int s = m0 + tid; tok[tid] = (s < C_) ? g_s2t[be*C_ + s] : -1; }
    __syncthreads();

    const float* Wb = Wg + (size_t)e * KDIM * LDB + n0;

    // A copy: 512 16B-chunks/stage; thread handles chunks {tid, tid+256}: row=c>>2, kc=c&3
    int ar0 = tid >> 2, ar1 = (tid + 256) >> 2, akc = (tid & 3);
    // B copy: 512 chunks; row=c>>5, col=c&31
    int br0 = tid >> 5, br1 = (tid + 256) >> 5, bc = (tid & 31);

    const float* aS0; const float* aS1; int az0, az1;
    if (IS_G1) {
        int t0 = tok[ar0], t1 = tok[ar1];
        aS0 = (t0 >= 0) ? g_xt + ((size_t)(b*N_ + t0) * D_ + akc*4) : g_xt;
        aS1 = (t1 >= 0) ? g_xt + ((size_t)(b*N_ + t1) * D_ + akc*4) : g_xt;
        az0 = (t0 >= 0) ? 16 : 0;  az1 = (t1 >= 0) ? 16 : 0;
    } else {
        int s0 = m0 + ar0, s1 = m0 + ar1;
        aS0 = (s0 < C_) ? g_Y + ((size_t)be*C_ + s0) * H_ + akc*4 : g_Y;
        aS1 = (s1 < C_) ? g_Y + ((size_t)be*C_ + s1) * H_ + akc*4 : g_Y;
        az0 = (s0 < C_) ? 16 : 0;  az1 = (s1 < C_) ? 16 : 0;
    }

    unsigned saA0 = (unsigned)__cvta_generic_to_shared(&As[0][ar0][akc*4]);
    unsigned saA1 = (unsigned)__cvta_generic_to_shared(&As[0][ar1][akc*4]);
    unsigned saB0 = (unsigned)__cvta_generic_to_shared(&Bs[0][br0][bc*4]);
    unsigned saB1 = (unsigned)__cvta_generic_to_shared(&Bs[0][br1][bc*4]);
    constexpr unsigned A_ST = 128*20*4, B_ST = 16*136*4;

    float acc[4][4][4];
#pragma unroll
    for (int i = 0; i < 4; i++)
#pragma unroll
        for (int j = 0; j < 4; j++)
#pragma unroll
            for (int k = 0; k < 4; k++) acc[i][j][k] = 0.f;

    // prologue: stage 0
    cp16(saA0, aS0, az0); cp16(saA1, aS1, az1);
    cp16(saB0, Wb + (size_t)br0 * LDB + bc*4, 16);
    cp16(saB1, Wb + (size_t)br1 * LDB + bc*4, 16);
    cpcommit();

    int wm = wid & 1, wn = wid >> 1;
    int gq = lane >> 2, t4 = lane & 3;

    for (int it = 0; it < ITERS; ++it) {
        int cur = it & 1;
        if (it + 1 < ITERS) {
            int k0 = (it + 1) * 16;
            unsigned so = (cur ^ 1) ? 1u : 0u;
            cp16(saA0 + so*A_ST, aS0 + k0, az0);
            cp16(saA1 + so*A_ST, aS1 + k0, az1);
            cp16(saB0 + so*B_ST, Wb + (size_t)(k0 + br0) * LDB + bc*4, 16);
            cp16(saB1 + so*B_ST, Wb + (size_t)(k0 + br1) * LDB + bc*4, 16);
            cpcommit();
            cpwait<1>();
        } else {
            cpwait<0>();
        }
        __syncthreads();

#pragma unroll
        for (int s = 0; s < 2; s++) {
            unsigned a[4][4], bf[4][2];
            int kk = s*8 + t4;
#pragma unroll
            for (int mt = 0; mt < 4; mt++) {
                int rm = wm*64 + mt*16 + gq;
                a[mt][0] = *(const unsigned*)&As[cur][rm  ][kk  ];
                a[mt][1] = *(const unsigned*)&As[cur][rm+8][kk  ];
                a[mt][2] = *(const unsigned*)&As[cur][rm  ][kk+4];
                a[mt][3] = *(const unsigned*)&As[cur][rm+8][kk+4];
            }
#pragma unroll
            for (int nt = 0; nt < 4; nt++) {
                int nn = wn*32 + nt*8 + gq;
                bf[nt][0] = f2tf32(Bs[cur][s*8 + t4    ][nn]);
                bf[nt][1] = f2tf32(Bs[cur][s*8 + t4 + 4][nn]);
            }
#pragma unroll
            for (int mt = 0; mt < 4; mt++)
#pragma unroll
                for (int nt = 0; nt < 4; nt++) mma8(acc[mt][nt], a[mt], bf[nt]);
        }
        __syncthreads();
    }

    // ---------------- epilogue ----------------
    if (IS_G1) {
#pragma unroll
        for (int mt = 0; mt < 4; mt++) {
            int r = wm*64 + mt*16 + gq;
            int s1 = m0 + r, s2 = s1 + 8;
#pragma unroll
            for (int nt = 0; nt < 4; nt++) {
                int gn = n0 + wn*32 + nt*8 + 2*t4;
                float2 bv = *(const float2*)&bias[(size_t)e*H_ + gn];
                if (s1 < C_) {
                    float2 v;
                    v.x = __uint_as_float(f2tf32(gelu_tanh(acc[mt][nt][0] + bv.x)));
                    v.y = __uint_as_float(f2tf32(gelu_tanh(acc[mt][nt][1] + bv.y)));
                    *(float2*)&g_Y[((size_t)be*C_ + s1)*H_ + gn] = v;
                }
                if (s2 < C_) {
                    float2 v;
                    v.x = __uint_as_float(f2tf32(gelu_tanh(acc[mt][nt][2] + bv.x)));
                    v.y = __uint_as_float(f2tf32(gelu_tanh(acc[mt][nt][3] + bv.y)));
                    *(float2*)&g_Y[((size_t)be*C_ + s2)*H_ + gn] = v;
                }
            }
        }
    } else {
#pragma unroll
        for (int mt = 0; mt < 4; mt++) {
            int r = wm*64 + mt*16 + gq;
            int tk1 = tok[r], tk2 = tok[r + 8];
            float gv1 = (tk1 >= 0) ? g_gate[b*N_ + tk1] : 0.f;
            float gv2 = (tk2 >= 0) ? g_gate[b*N_ + tk2] : 0.f;
#pragma unroll
            for (int nt = 0; nt < 4; nt++) {
                int gn = n0 + wn*32 + nt*8 + 2*t4;
                float2 bv = *(const float2*)&bias[(size_t)e*D_ + gn];
                if (tk1 >= 0) {
                    float2 v = { gv1*(acc[mt][nt][0] + bv.x), gv1*(acc[mt][nt][1] + bv.y) };
                    *(float2*)&outp[((size_t)(b*N_ + tk1))*D_ + gn] = v;
                }
                if (tk2 >= 0) {
                    float2 v = { gv2*(acc[mt][nt][2] + bv.x), gv2*(acc[mt][nt][3] + bv.y) };
                    *(float2*)&outp[((size_t)(b*N_ + tk2))*D_ + gn] = v;
                }
            }
        }
    }
}

// ---------------- launch ----------------
extern "C" void kernel_launch(void* const* d_in, const int* in_sizes, int n_in,
                              void* d_out, int out_size) {
    const float* x  = (const float*)d_in[0];
    const float* wr = (const float*)d_in[1];
    const float* w1 = (const float*)d_in[2];
    const float* b1 = (const float*)d_in[3];
    const float* w2 = (const float*)d_in[4];
    const float* b2 = (const float*)d_in[5];
    float* out = (float*)d_out;

    cudaMemsetAsync(out, 0, (size_t)out_size * sizeof(float), 0);
    k_init<<<(B_*E_*C_ + 255) / 256, 256>>>();
    k_cvtx<<<(BN_TOK * D_ / 4) / 256, 256>>>(x);
    k_router<<<BN_TOK, 128>>>(x, wr);
    k_scan<<<B_*E_, 32>>>();
    k_final<<<1, 1>>>(out);
    k_mma<true ><<<dim3(H_/128, 3, B_*E_), 256>>>(w1, b1, nullptr);
    k_mma<false><<<dim3(D_/128, 3, B_*E_), 256>>>(w2, b2, out);
}

// round 3
// speedup vs baseline: 3.9769x; 1.1975x over previous
#include <cuda_runtime.h>
#include <math.h>

#define B_  4
#define N_  2048
#define D_  1024
#define E_  8
#define H_  4096
#define C_  320
#define BN_TOK (B_*N_)

// -------- scratch (device globals: allocation-free) --------
__device__ float g_Y[(size_t)B_*E_*C_*H_];   // expert hidden (tf32-rounded fp32)
__device__ float g_xt[(size_t)BN_TOK*D_];    // x pre-rounded to tf32
__device__ int   g_s2t[B_*E_*C_];            // slot -> token (or -1)
__device__ int   g_cnt[B_*E_];
__device__ float g_proxy[B_*E_];
__device__ float g_gate[BN_TOK];
__device__ int   g_idx[BN_TOK];
__device__ float g_z2;

// ---------------- helpers ----------------
__device__ __forceinline__ unsigned f2tf32(float f) {
    unsigned u; asm("cvt.rna.tf32.f32 %0, %1;" : "=r"(u) : "f"(f)); return u;
}
__device__ __forceinline__ void mma8(float c[4], const unsigned a[4], const unsigned b[2]) {
    asm volatile("mma.sync.aligned.m16n8k8.row.col.f32.tf32.tf32.f32 "
                 "{%0,%1,%2,%3},{%4,%5,%6,%7},{%8,%9},{%0,%1,%2,%3};"
                 : "+f"(c[0]), "+f"(c[1]), "+f"(c[2]), "+f"(c[3])
                 : "r"(a[0]), "r"(a[1]), "r"(a[2]), "r"(a[3]), "r"(b[0]), "r"(b[1]));
}
__device__ __forceinline__ void cp16(unsigned saddr, const void* g, int sz) {
    asm volatile("cp.async.cg.shared.global [%0], [%1], 16, %2;"
                 :: "r"(saddr), "l"(g), "r"(sz));
}
__device__ __forceinline__ void cpcommit() { asm volatile("cp.async.commit_group;"); }
template<int n> __device__ __forceinline__ void cpwait() {
    asm volatile("cp.async.wait_group %0;" :: "n"(n));
}
__device__ __forceinline__ float gelu_tanh(float v) {
    float v3 = v * v * v;
    return 0.5f * v * (1.f + tanhf(0.7978845608028654f * (v + 0.044715f * v3)));
}

// ---------------- init ----------------
__global__ void k_init() {
    int i = blockIdx.x * blockDim.x + threadIdx.x;
    if (i < B_*E_*C_) g_s2t[i] = -1;
    if (i < B_*E_)    g_proxy[i] = 0.f;
    if (i == 0)       g_z2 = 0.f;
}

// ---------------- router (+ fused x->tf32 conversion) ----------------
__global__ void k_router(const float* __restrict__ x, const float* __restrict__ wr) {
    int t = blockIdx.x;
    int b = t / N_;
    const float* xr = x + (size_t)t * D_;
    float* xtr = g_xt + (size_t)t * D_;
    float acc[E_];
#pragma unroll
    for (int e = 0; e < E_; e++) acc[e] = 0.f;
    for (int d = threadIdx.x; d < D_; d += blockDim.x) {
        float xv = __ldg(xr + d);
        xtr[d] = __uint_as_float(f2tf32(xv));      // fused tf32 pre-round
        const float4* w4 = (const float4*)(wr + (size_t)d * E_);
        float4 w0 = w4[0], w1 = w4[1];
        acc[0] += xv * w0.x; acc[1] += xv * w0.y;
        acc[2] += xv * w0.z; acc[3] += xv * w0.w;
        acc[4] += xv * w1.x; acc[5] += xv * w1.y;
        acc[6] += xv * w1.z; acc[7] += xv * w1.w;
    }
    __shared__ float sh[4][E_];
    int lane = threadIdx.x & 31, warp = threadIdx.x >> 5;
#pragma unroll
    for (int e = 0; e < E_; e++) {
        float v = acc[e];
#pragma unroll
        for (int off = 16; off > 0; off >>= 1) v += __shfl_down_sync(0xffffffffu, v, off);
        if (lane == 0) sh[warp][e] = v;
    }
    __syncthreads();
    if (threadIdx.x == 0) {
        float logits[E_];
#pragma unroll
        for (int e = 0; e < E_; e++) logits[e] = sh[0][e] + sh[1][e] + sh[2][e] + sh[3][e];
        float maxl = logits[0]; int amax = 0;
#pragma unroll
        for (int e = 1; e < E_; e++) if (logits[e] > maxl) { maxl = logits[e]; amax = e; }
        float sum = 0.f, p[E_];
#pragma unroll
        for (int e = 0; e < E_; e++) { p[e] = expf(logits[e] - maxl); sum += p[e]; }
        float inv = 1.f / sum;
        float z = maxl + logf(sum);
#pragma unroll
        for (int e = 0; e < E_; e++) atomicAdd(&g_proxy[b*E_ + e], p[e] * inv);
        atomicAdd(&g_z2, z * z);
        g_idx[t]  = amax;
        g_gate[t] = p[amax] * inv;
    }
}

// ---------------- capacity scan (MLP=8 prefetch) ----------------
__global__ void k_scan() {
    int be = blockIdx.x;
    int b = be / E_, e = be % E_;
    int lane = threadIdx.x;
    unsigned lt = (1u << lane) - 1u;
    int base = 0;
    for (int n0 = 0; n0 < N_; n0 += 256) {
        int v[8];
#pragma unroll
        for (int u = 0; u < 8; u++) v[u] = __ldg(&g_idx[b*N_ + n0 + u*32 + lane]);
#pragma unroll
        for (int u = 0; u < 8; u++) {
            int pred = (v[u] == e);
            unsigned bal = __ballot_sync(0xffffffffu, pred);
            if (pred) {
                int slot = base + __popc(bal & lt);
                if (slot < C_) g_s2t[be*C_ + slot] = n0 + u*32 + lane;
            }
            base += __popc(bal);
        }
    }
    if (lane == 0) g_cnt[be] = base;
}

// ---------------- scalar losses ----------------
__global__ void k_final(float* __restrict__ out) {
    float aux = 0.f;
    for (int be = 0; be < B_*E_; be++)
        aux += ((float)g_cnt[be] / (float)N_) * (g_proxy[be] / (float)N_);
    aux *= (float)(E_*E_) / (float)B_;
    out[(size_t)BN_TOK * D_]     = aux;
    out[(size_t)BN_TOK * D_ + 1] = g_z2 / (float)BN_TOK;
}

// ---------------- tf32 mma GEMM: BM=64 BN=128 BK=16, 4 warps (2x2), warp 32x64 ----------------
// 3-stage cp.async pipeline, one __syncthreads per k-iter, zero wasted M rows (grid.y=5).
// IS_G1: A = gather(g_xt) [C,D], B = w1[e] [D,H]; out: g_Y = tf32(gelu(acc + b1))
// !IS_G1: A = g_Y [C,H], B = w2[e] [H,D]; out: scatter gate*(acc + b2) to out
template<bool IS_G1>
__global__ void __launch_bounds__(128, 2) k_mma(const float* __restrict__ Wg,
                                                const float* __restrict__ bias,
                                                float* __restrict__ outp)
{
    constexpr int LDB  = IS_G1 ? H_ : D_;
    constexpr int KDIM = IS_G1 ? D_ : H_;
    constexpr int ITERS = KDIM / 16;

    __shared__ float As[3][64][20];     // [stage][m][k], pad 20 -> conflict-free
    __shared__ float Bs[3][16][136];    // [stage][k][n], pad 8 -> conflict-free
    __shared__ int   tok[64];

    int be = blockIdx.z, b = be >> 3, e = be & 7;
    int m0 = blockIdx.y * 64, n0 = blockIdx.x * 128;
    int tid = threadIdx.x, lane = tid & 31, wid = tid >> 5;

    if (tid < 64) tok[tid] = g_s2t[be*C_ + m0 + tid];
    __syncthreads();

    const float* Wb = Wg + (size_t)e * KDIM * LDB + n0;

    // A copy: 256 16B chunks/stage; thread -> chunks {tid, tid+128}: row=c>>2, kc=c&3
    int ar0 = tid >> 2, ar1 = ar0 + 32, akc = (tid & 3);
    // B copy: 512 chunks/stage; thread -> 4 chunks: row = tid>>5 + 4j, col = tid&31
    int brr = tid >> 5, bc = tid & 31;

    const float* aS0; const float* aS1; int az0, az1;
    if (IS_G1) {
        int t0 = tok[ar0], t1 = tok[ar1];
        aS0 = (t0 >= 0) ? g_xt + ((size_t)(b*N_ + t0) * D_ + akc*4) : g_xt;
        aS1 = (t1 >= 0) ? g_xt + ((size_t)(b*N_ + t1) * D_ + akc*4) : g_xt;
        az0 = (t0 >= 0) ? 16 : 0;  az1 = (t1 >= 0) ? 16 : 0;
    } else {
        aS0 = g_Y + ((size_t)be*C_ + m0 + ar0) * H_ + akc*4;
        aS1 = g_Y + ((size_t)be*C_ + m0 + ar1) * H_ + akc*4;
        az0 = 16; az1 = 16;
    }

    unsigned saA0 = (unsigned)__cvta_generic_to_shared(&As[0][ar0][akc*4]);
    unsigned saA1 = (unsigned)__cvta_generic_to_shared(&As[0][ar1][akc*4]);
    unsigned saB0 = (unsigned)__cvta_generic_to_shared(&Bs[0][brr][bc*4]);
    constexpr unsigned A_ST = 64*20*4, B_ST = 16*136*4;

    float acc[2][8][4];
#pragma unroll
    for (int i = 0; i < 2; i++)
#pragma unroll
        for (int j = 0; j < 8; j++)
#pragma unroll
            for (int k = 0; k < 4; k++) acc[i][j][k] = 0.f;

    // prologue: stages 0, 1
#pragma unroll
    for (int st = 0; st < 2; st++) {
        int k0 = st * 16;
        cp16(saA0 + st*A_ST, aS0 + k0, az0);
        cp16(saA1 + st*A_ST, aS1 + k0, az1);
#pragma unroll
        for (int j = 0; j < 4; j++)
            cp16(saB0 + st*B_ST + j*4*136*4,
                 Wb + (size_t)(k0 + brr + 4*j) * LDB + bc*4, 16);
        cpcommit();
    }

    int wm = wid & 1, wn = wid >> 1;
    int gq = lane >> 2, t4 = lane & 3;

    for (int it = 0; it < ITERS; ++it) {
        int cur = it % 3;
        cpwait<1>();
        __syncthreads();

        int nxt = it + 2;
        if (nxt < ITERS) {
            int so = nxt % 3;
            int k0 = nxt * 16;
            cp16(saA0 + so*A_ST, aS0 + k0, az0);
            cp16(saA1 + so*A_ST, aS1 + k0, az1);
#pragma unroll
            for (int j = 0; j < 4; j++)
                cp16(saB0 + so*B_ST + j*4*136*4,
                     Wb + (size_t)(k0 + brr + 4*j) * LDB + bc*4, 16);
        }
        cpcommit();

#pragma unroll
        for (int s = 0; s < 2; s++) {
            unsigned a[2][4], bf[8][2];
            int kk = s*8 + t4;
#pragma unroll
            for (int mt = 0; mt < 2; mt++) {
                int rm = wm*32 + mt*16 + gq;
                a[mt][0] = *(const unsigned*)&As[cur][rm  ][kk  ];
                a[mt][1] = *(const unsigned*)&As[cur][rm+8][kk  ];
                a[mt][2] = *(const unsigned*)&As[cur][rm  ][kk+4];
                a[mt][3] = *(const unsigned*)&As[cur][rm+8][kk+4];
            }
#pragma unroll
            for (int nt = 0; nt < 8; nt++) {
                int nn = wn*64 + nt*8 + gq;
                bf[nt][0] = f2tf32(Bs[cur][s*8 + t4    ][nn]);
                bf[nt][1] = f2tf32(Bs[cur][s*8 + t4 + 4][nn]);
            }
#pragma unroll
            for (int mt = 0; mt < 2; mt++)
#pragma unroll
                for (int nt = 0; nt < 8; nt++) mma8(acc[mt][nt], a[mt], bf[nt]);
        }
    }

    // ---------------- epilogue ----------------
    if (IS_G1) {
#pragma unroll
        for (int mt = 0; mt < 2; mt++) {
            int r1 = m0 + wm*32 + mt*16 + gq, r2 = r1 + 8;
#pragma unroll
            for (int nt = 0; nt < 8; nt++) {
                int gn = n0 + wn*64 + nt*8 + 2*t4;
                float2 bv = *(const float2*)&bias[(size_t)e*H_ + gn];
                float2 v1, v2;
                v1.x = __uint_as_float(f2tf32(gelu_tanh(acc[mt][nt][0] + bv.x)));
                v1.y = __uint_as_float(f2tf32(gelu_tanh(acc[mt][nt][1] + bv.y)));
                v2.x = __uint_as_float(f2tf32(gelu_tanh(acc[mt][nt][2] + bv.x)));
                v2.y = __uint_as_float(f2tf32(gelu_tanh(acc[mt][nt][3] + bv.y)));
                *(float2*)&g_Y[((size_t)be*C_ + r1)*H_ + gn] = v1;
                *(float2*)&g_Y[((size_t)be*C_ + r2)*H_ + gn] = v2;
            }
        }
    } else {
#pragma unroll
        for (int mt = 0; mt < 2; mt++) {
            int r = wm*32 + mt*16 + gq;
            int tk1 = tok[r], tk2 = tok[r + 8];
            float gv1 = (tk1 >= 0) ? g_gate[b*N_ + tk1] : 0.f;
            float gv2 = (tk2 >= 0) ? g_gate[b*N_ + tk2] : 0.f;
#pragma unroll
            for (int nt = 0; nt < 8; nt++) {
                int gn = n0 + wn*64 + nt*8 + 2*t4;
                float2 bv = *(const float2*)&bias[(size_t)e*D_ + gn];
                if (tk1 >= 0) {
                    float2 v = { gv1*(acc[mt][nt][0] + bv.x), gv1*(acc[mt][nt][1] + bv.y) };
                    *(float2*)&outp[((size_t)(b*N_ + tk1))*D_ + gn] = v;
                }
                if (tk2 >= 0) {
                    float2 v = { gv2*(acc[mt][nt][2] + bv.x), gv2*(acc[mt][nt][3] + bv.y) };
                    *(float2*)&outp[((size_t)(b*N_ + tk2))*D_ + gn] = v;
                }
            }
        }
    }
}

// ---------------- launch ----------------
extern "C" void kernel_launch(void* const* d_in, const int* in_sizes, int n_in,
                              void* d_out, int out_size) {
    const float* x  = (const float*)d_in[0];
    const float* wr = (const float*)d_in[1];
    const float* w1 = (const float*)d_in[2];
    const float* b1 = (const float*)d_in[3];
    const float* w2 = (const float*)d_in[4];
    const float* b2 = (const float*)d_in[5];
    float* out = (float*)d_out;

    cudaMemsetAsync(out, 0, (size_t)out_size * sizeof(float), 0);
    k_init<<<(B_*E_*C_ + 255) / 256, 256>>>();
    k_router<<<BN_TOK, 128>>>(x, wr);
    k_scan<<<B_*E_, 32>>>();
    k_final<<<1, 1>>>(out);
    k_mma<true ><<<dim3(H_/128, C_/64, B_*E_), 128>>>(w1, b1, nullptr);
    k_mma<false><<<dim3(D_/128, C_/64, B_*E_), 128>>>(w2, b2, out);
}

// round 5
// speedup vs baseline: 5.5231x; 1.3888x over previous
#include <cuda_runtime.h>
#include <cuda_fp16.h>
#include <math.h>
#include <stdint.h>

#define B_  4
#define N_  2048
#define D_  1024
#define E_  8
#define H_  4096
#define C_  320
#define BN_TOK (B_*N_)

// -------- scratch (device globals: allocation-free) --------
__device__ __half g_Yh[(size_t)B_*E_*C_*H_];   // expert hidden, fp16
__device__ __half g_xh[(size_t)BN_TOK*D_];     // x in fp16
__device__ __half g_w1t[(size_t)E_*H_*D_];     // w1 transposed: [E][H][D] fp16 (K-major)
__device__ __half g_w2t[(size_t)E_*D_*H_];     // w2 transposed: [E][D][H] fp16 (K-major)
__device__ int    g_s2t[B_*E_*C_];
__device__ int    g_cnt[B_*E_];
__device__ float  g_proxy[B_*E_];
__device__ float  g_gate[BN_TOK];
__device__ int    g_idx[BN_TOK];
__device__ float  g_z2;

// ---------------- helpers ----------------
__device__ __forceinline__ void mma16(float c[4], const unsigned a[4], const unsigned b[2]) {
    asm volatile("mma.sync.aligned.m16n8k16.row.col.f32.f16.f16.f32 "
                 "{%0,%1,%2,%3},{%4,%5,%6,%7},{%8,%9},{%0,%1,%2,%3};"
                 : "+f"(c[0]), "+f"(c[1]), "+f"(c[2]), "+f"(c[3])
                 : "r"(a[0]), "r"(a[1]), "r"(a[2]), "r"(a[3]), "r"(b[0]), "r"(b[1]));
}
__device__ __forceinline__ void cp16(unsigned saddr, const void* g, int sz) {
    asm volatile("cp.async.cg.shared.global [%0], [%1], 16, %2;"
                 :: "r"(saddr), "l"(g), "r"(sz));
}
__device__ __forceinline__ void cpcommit() { asm volatile("cp.async.commit_group;"); }
template<int n> __device__ __forceinline__ void cpwait() {
    asm volatile("cp.async.wait_group %0;" :: "n"(n));
}
__device__ __forceinline__ float gelu_tanh(float v) {
    float v3 = v * v * v;
    return 0.5f * v * (1.f + tanhf(0.7978845608028654f * (v + 0.044715f * v3)));
}

// ---------------- init ----------------
__global__ void k_init() {
    int i = blockIdx.x * blockDim.x + threadIdx.x;
    if (i < B_*E_*C_) g_s2t[i] = -1;
    if (i < B_*E_)    g_proxy[i] = 0.f;
    if (i == 0)       g_z2 = 0.f;
}

// ---------------- weight transposes -> fp16 K-major ----------------
__global__ void k_tr1(const float* __restrict__ w) {   // w1 [E][D][H] -> g_w1t [E][H][D]
    __shared__ float s[32][33];
    int e = blockIdx.z, h0 = blockIdx.x*32, d0 = blockIdx.y*32;
    const float* S = w + (size_t)e * D_ * H_;
    __half* Dt = g_w1t + (size_t)e * H_ * D_;
    int x = threadIdx.x, y = threadIdx.y;
#pragma unroll
    for (int i = 0; i < 4; i++) s[y+8*i][x] = S[(size_t)(d0+y+8*i)*H_ + h0 + x];
    __syncthreads();
#pragma unroll
    for (int i = 0; i < 4; i++)
        Dt[(size_t)(h0+y+8*i)*D_ + d0 + x] = __float2half(s[x][y+8*i]);
}
__global__ void k_tr2(const float* __restrict__ w) {   // w2 [E][H][D] -> g_w2t [E][D][H]
    __shared__ float s[32][33];
    int e = blockIdx.z, d0 = blockIdx.x*32, h0 = blockIdx.y*32;
    const float* S = w + (size_t)e * H_ * D_;
    __half* Dt = g_w2t + (size_t)e * D_ * H_;
    int x = threadIdx.x, y = threadIdx.y;
#pragma unroll
    for (int i = 0; i < 4; i++) s[y+8*i][x] = S[(size_t)(h0+y+8*i)*D_ + d0 + x];
    __syncthreads();
#pragma unroll
    for (int i = 0; i < 4; i++)
        Dt[(size_t)(d0+y+8*i)*H_ + h0 + x] = __float2half(s[x][y+8*i]);
}

// ---------------- router (+ fused x->fp16) ----------------
__global__ void k_router(const float* __restrict__ x, const float* __restrict__ wr) {
    int t = blockIdx.x;
    int b = t / N_;
    const float* xr = x + (size_t)t * D_;
    __half* xtr = g_xh + (size_t)t * D_;
    float acc[E_];
#pragma unroll
    for (int e = 0; e < E_; e++) acc[e] = 0.f;
    for (int d = threadIdx.x; d < D_; d += blockDim.x) {
        float xv = __ldg(xr + d);
        xtr[d] = __float2half(xv);
        const float4* w4 = (const float4*)(wr + (size_t)d * E_);
        float4 w0 = w4[0], w1 = w4[1];
        acc[0] += xv * w0.x; acc[1] += xv * w0.y;
        acc[2] += xv * w0.z; acc[3] += xv * w0.w;
        acc[4] += xv * w1.x; acc[5] += xv * w1.y;
        acc[6] += xv * w1.z; acc[7] += xv * w1.w;
    }
    __shared__ float sh[4][E_];
    int lane = threadIdx.x & 31, warp = threadIdx.x >> 5;
#pragma unroll
    for (int e = 0; e < E_; e++) {
        float v = acc[e];
#pragma unroll
        for (int off = 16; off > 0; off >>= 1) v += __shfl_down_sync(0xffffffffu, v, off);
        if (lane == 0) sh[warp][e] = v;
    }
    __syncthreads();
    if (threadIdx.x == 0) {
        float logits[E_];
#pragma unroll
        for (int e = 0; e < E_; e++) logits[e] = sh[0][e] + sh[1][e] + sh[2][e] + sh[3][e];
        float maxl = logits[0]; int amax = 0;
#pragma unroll
        for (int e = 1; e < E_; e++) if (logits[e] > maxl) { maxl = logits[e]; amax = e; }
        float sum = 0.f, p[E_];
#pragma unroll
        for (int e = 0; e < E_; e++) { p[e] = expf(logits[e] - maxl); sum += p[e]; }
        float inv = 1.f / sum;
        float z = maxl + logf(sum);
#pragma unroll
        for (int e = 0; e < E_; e++) atomicAdd(&g_proxy[b*E_ + e], p[e] * inv);
        atomicAdd(&g_z2, z * z);
        g_idx[t]  = amax;
        g_gate[t] = p[amax] * inv;
    }
}

// ---------------- capacity scan ----------------
__global__ void k_scan() {
    int be = blockIdx.x;
    int b = be / E_, e = be % E_;
    int lane = threadIdx.x;
    unsigned lt = (1u << lane) - 1u;
    int base = 0;
    for (int n0 = 0; n0 < N_; n0 += 256) {
        int v[8];
#pragma unroll
        for (int u = 0; u < 8; u++) v[u] = __ldg(&g_idx[b*N_ + n0 + u*32 + lane]);
#pragma unroll
        for (int u = 0; u < 8; u++) {
            int pred = (v[u] == e);
            unsigned bal = __ballot_sync(0xffffffffu, pred);
            if (pred) {
                int slot = base + __popc(bal & lt);
                if (slot < C_) g_s2t[be*C_ + slot] = n0 + u*32 + lane;
            }
            base += __popc(bal);
        }
    }
    if (lane == 0) g_cnt[be] = base;
}

// ---------------- scalar losses ----------------
__global__ void k_final(float* __restrict__ out) {
    float aux = 0.f;
    for (int be = 0; be < B_*E_; be++)
        aux += ((float)g_cnt[be] / (float)N_) * (g_proxy[be] / (float)N_);
    aux *= (float)(E_*E_) / (float)B_;
    out[(size_t)BN_TOK * D_]     = aux;
    out[(size_t)BN_TOK * D_ + 1] = g_z2 / (float)BN_TOK;
}

// ---------------- fp16 mma GEMM: BM=64 BN=128 BK=32, 4 warps (2x2), warp 32x64 ----------------
// SMEM: As[64][k32] pitch 40 halves, Bs[128][k32] pitch 40 halves (K-major, conflict-free frags)
// IS_G1: A = gather(g_xh)[C,D], B = g_w1t[e][H][D]; g_Yh = fp16(gelu(acc + b1))
// else:  A = g_Yh[C,H],         B = g_w2t[e][D][H]; out = scatter gate*(acc + b2)
#define PA 40   // pitch in halves (80 bytes)

template<bool IS_G1>
__global__ void __launch_bounds__(128, 2) k_mma(const float* __restrict__ bias,
                                                float* __restrict__ outp)
{
    constexpr int KDIM  = IS_G1 ? D_ : H_;
    constexpr int ITERS = KDIM / 32;
    constexpr int AS_H = 64*PA, BS_H = 128*PA;   // halves per stage

    __shared__ __align__(16) __half As[3*AS_H];
    __shared__ __align__(16) __half Bs[3*BS_H];
    __shared__ int tok[64];

    int be = blockIdx.z, b = be >> 3, e = be & 7;
    int m0 = blockIdx.y * 64, n0 = blockIdx.x * 128;
    int tid = threadIdx.x, lane = tid & 31, wid = tid >> 5;

    if (tid < 64) tok[tid] = g_s2t[be*C_ + m0 + tid];
    __syncthreads();

    // A copy: 256 16B chunks (64 rows x 4); thread -> chunks {tid, tid+128}
    int ar0 = tid >> 2, ar1 = ar0 + 32, akc = tid & 3;   // kc*8 halves
    // B copy: 512 chunks (128 rows x 4); thread -> rows (tid>>2)+32j, kc = tid&3
    int br0 = tid >> 2, bkc = tid & 3;

    const __half* aS0; const __half* aS1; int az0, az1;
    if (IS_G1) {
        int t0 = tok[ar0], t1 = tok[ar1];
        aS0 = (t0 >= 0) ? g_xh + ((size_t)(b*N_ + t0) * D_ + akc*8) : g_xh;
        aS1 = (t1 >= 0) ? g_xh + ((size_t)(b*N_ + t1) * D_ + akc*8) : g_xh;
        az0 = (t0 >= 0) ? 16 : 0;  az1 = (t1 >= 0) ? 16 : 0;
    } else {
        aS0 = g_Yh + ((size_t)be*C_ + m0 + ar0) * H_ + akc*8;
        aS1 = g_Yh + ((size_t)be*C_ + m0 + ar1) * H_ + akc*8;
        az0 = 16; az1 = 16;
    }
    const __half* wt = IS_G1 ? g_w1t : g_w2t;
    const __half* wbase = wt + (size_t)e * (IS_G1 ? (size_t)H_*D_ : (size_t)D_*H_)
                        + (size_t)(n0 + br0) * KDIM + bkc*8;

    unsigned saA0 = (unsigned)__cvta_generic_to_shared(&As[ar0*PA + akc*8]);
    unsigned saA1 = (unsigned)__cvta_generic_to_shared(&As[ar1*PA + akc*8]);
    unsigned saB0 = (unsigned)__cvta_generic_to_shared(&Bs[br0*PA + bkc*8]);
    constexpr unsigned A_ST = AS_H*2, B_ST = BS_H*2;

    auto fill = [&](int st, int k0) {
        cp16(saA0 + st*A_ST, aS0 + k0, az0);
        cp16(saA1 + st*A_ST, aS1 + k0, az1);
#pragma unroll
        for (int j = 0; j < 4; j++)
            cp16(saB0 + st*B_ST + j*32*PA*2, wbase + (size_t)32*j*KDIM + k0, 16);
        cpcommit();
    };

    float acc[2][8][4];
#pragma unroll
    for (int i = 0; i < 2; i++)
#pragma unroll
        for (int j = 0; j < 8; j++)
#pragma unroll
            for (int k = 0; k < 4; k++) acc[i][j][k] = 0.f;

    fill(0, 0);
    fill(1, 32);

    int wm = wid & 1, wn = wid >> 1;
    int gq = lane >> 2, t4 = lane & 3;

    for (int it = 0; it < ITERS; ++it) {
        int cur = it % 3;
        cpwait<1>();
        __syncthreads();

        int nxt = it + 2;
        if (nxt < ITERS) fill(nxt % 3, nxt * 32);
        else cpcommit();

        const __half* Ac = &As[cur*AS_H];
        const __half* Bc = &Bs[cur*BS_H];
#pragma unroll
        for (int s = 0; s < 2; s++) {
            unsigned a[2][4], bf[8][2];
            int kh = s*16 + 2*t4;     // half offset within row
#pragma unroll
            for (int mt = 0; mt < 2; mt++) {
                int rm = wm*32 + mt*16 + gq;
                a[mt][0] = *(const unsigned*)&Ac[rm*PA + kh];
                a[mt][1] = *(const unsigned*)&Ac[(rm+8)*PA + kh];
                a[mt][2] = *(const unsigned*)&Ac[rm*PA + kh + 8];
                a[mt][3] = *(const unsigned*)&Ac[(rm+8)*PA + kh + 8];
            }
#pragma unroll
            for (int nt = 0; nt < 8; nt++) {
                int nn = wn*64 + nt*8 + gq;
                bf[nt][0] = *(const unsigned*)&Bc[nn*PA + kh];
                bf[nt][1] = *(const unsigned*)&Bc[nn*PA + kh + 8];
            }
#pragma unroll
            for (int mt = 0; mt < 2; mt++)
#pragma unroll
                for (int nt = 0; nt < 8; nt++) mma16(acc[mt][nt], a[mt], bf[nt]);
        }
    }

    // ---------------- epilogue ----------------
    if (IS_G1) {
#pragma unroll
        for (int mt = 0; mt < 2; mt++) {
            int r1 = m0 + wm*32 + mt*16 + gq, r2 = r1 + 8;
#pragma unroll
            for (int nt = 0; nt < 8; nt++) {
                int gn = n0 + wn*64 + nt*8 + 2*t4;
                float2 bv = *(const float2*)&bias[(size_t)e*H_ + gn];
                __half2 v1, v2;
                v1.x = __float2half(gelu_tanh(acc[mt][nt][0] + bv.x));
                v1.y = __float2half(gelu_tanh(acc[mt][nt][1] + bv.y));
                v2.x = __float2half(gelu_tanh(acc[mt][nt][2] + bv.x));
                v2.y = __float2half(gelu_tanh(acc[mt][nt][3] + bv.y));
                *(__half2*)&g_Yh[((size_t)be*C_ + r1)*H_ + gn] = v1;
                *(__half2*)&g_Yh[((size_t)be*C_ + r2)*H_ + gn] = v2;
            }
        }
    } else {
#pragma unroll
        for (int mt = 0; mt < 2; mt++) {
            int r = wm*32 + mt*16 + gq;
            int tk1 = tok[r], tk2 = tok[r + 8];
            float gv1 = (tk1 >= 0) ? g_gate[b*N_ + tk1] : 0.f;
            float gv2 = (tk2 >= 0) ? g_gate[b*N_ + tk2] : 0.f;
#pragma unroll
            for (int nt = 0; nt < 8; nt++) {
                int gn = n0 + wn*64 + nt*8 + 2*t4;
                float2 bv = *(const float2*)&bias[(size_t)e*D_ + gn];
                if (tk1 >= 0) {
                    float2 v = { gv1*(acc[mt][nt][0] + bv.x), gv1*(acc[mt][nt][1] + bv.y) };
                    *(float2*)&outp[((size_t)(b*N_ + tk1))*D_ + gn] = v;
                }
                if (tk2 >= 0) {
                    float2 v = { gv2*(acc[mt][nt][2] + bv.x), gv2*(acc[mt][nt][3] + bv.y) };
                    *(float2*)&outp[((size_t)(b*N_ + tk2))*D_ + gn] = v;
                }
            }
        }
    }
}

// ---------------- launch ----------------
extern "C" void kernel_launch(void* const* d_in, const int* in_sizes, int n_in,
                              void* d_out, int out_size) {
    const float* x  = (const float*)d_in[0];
    const float* wr = (const float*)d_in[1];
    const float* w1 = (const float*)d_in[2];
    const float* b1 = (const float*)d_in[3];
    const float* w2 = (const float*)d_in[4];
    const float* b2 = (const float*)d_in[5];
    float* out = (float*)d_out;

    cudaMemsetAsync(out, 0, (size_t)out_size * sizeof(float), 0);
    k_init<<<(B_*E_*C_ + 255) / 256, 256>>>();
    k_tr1<<<dim3(H_/32, D_/32, E_), dim3(32, 8)>>>(w1);
    k_tr2<<<dim3(D_/32, H_/32, E_), dim3(32, 8)>>>(w2);
    k_router<<<BN_TOK, 128>>>(x, wr);
    k_scan<<<B_*E_, 32>>>();
    k_final<<<1, 1>>>(out);
    k_mma<true ><<<dim3(H_/128, C_/64, B_*E_), 128>>>(b1, nullptr);
    k_mma<false><<<dim3(D_/128, C_/64, B_*E_), 128>>>(b2, out);
}

// round 6
// speedup vs baseline: 6.1378x; 1.1113x over previous
#include <cuda_runtime.h>
#include <cuda_fp16.h>
#include <math.h>
#include <stdint.h>

#define B_  4
#define N_  2048
#define D_  1024
#define E_  8
#define H_  4096
#define C_  320
#define BN_TOK (B_*N_)

// -------- scratch (device globals: allocation-free) --------
__device__ __half g_Yh[(size_t)B_*E_*C_*H_];   // expert hidden, fp16
__device__ __half g_xh[(size_t)BN_TOK*D_];     // x in fp16
__device__ __half g_w1t[(size_t)E_*H_*D_];     // w1 transposed: [E][H][D] fp16 (K-major)
__device__ __half g_w2t[(size_t)E_*D_*H_];     // w2 transposed: [E][D][H] fp16 (K-major)
__device__ int    g_s2t[B_*E_*C_];
__device__ int    g_cnt[B_*E_];
__device__ float  g_proxy[B_*E_];
__device__ float  g_gate[BN_TOK];
__device__ int    g_idx[BN_TOK];
__device__ float  g_z2;

// ---------------- helpers ----------------
__device__ __forceinline__ void mma16(float c[4], const unsigned a[4], const unsigned b[2]) {
    asm volatile("mma.sync.aligned.m16n8k16.row.col.f32.f16.f16.f32 "
                 "{%0,%1,%2,%3},{%4,%5,%6,%7},{%8,%9},{%0,%1,%2,%3};"
                 : "+f"(c[0]), "+f"(c[1]), "+f"(c[2]), "+f"(c[3])
                 : "r"(a[0]), "r"(a[1]), "r"(a[2]), "r"(a[3]), "r"(b[0]), "r"(b[1]));
}
__device__ __forceinline__ void cp16(unsigned saddr, const void* g, int sz) {
    asm volatile("cp.async.cg.shared.global [%0], [%1], 16, %2;"
                 :: "r"(saddr), "l"(g), "r"(sz));
}
__device__ __forceinline__ void cpcommit() { asm volatile("cp.async.commit_group;"); }
template<int n> __device__ __forceinline__ void cpwait() {
    asm volatile("cp.async.wait_group %0;" :: "n"(n));
}
__device__ __forceinline__ float gelu_tanh(float v) {
    float v3 = v * v * v;
    return 0.5f * v * (1.f + tanhf(0.7978845608028654f * (v + 0.044715f * v3)));
}

// ---------------- init ----------------
__global__ void k_init() {
    int i = blockIdx.x * blockDim.x + threadIdx.x;
    if (i < B_*E_*C_) g_s2t[i] = -1;
    if (i < B_*E_)    g_proxy[i] = 0.f;
    if (i == 0)       g_z2 = 0.f;
}

// ---------------- weight transposes -> fp16 K-major (vectorized) ----------------
// 32x32 fp32 tile in smem (pitch 33, conflict-free both phases), 16B packed stores.
__global__ void __launch_bounds__(128) k_tr1(const float* __restrict__ w) {
    __shared__ float s[32][33];
    int e = blockIdx.z, h0 = blockIdx.x*32, d0 = blockIdx.y*32;
    const float* S = w + (size_t)e * D_ * H_;
    int tid = threadIdx.x;
#pragma unroll
    for (int it = 0; it < 2; it++) {
        int dr = (tid >> 3) + it*16;
        int hc = (tid & 7) * 4;
        float4 v = *(const float4*)&S[(size_t)(d0+dr)*H_ + h0 + hc];
        s[dr][hc] = v.x; s[dr][hc+1] = v.y; s[dr][hc+2] = v.z; s[dr][hc+3] = v.w;
    }
    __syncthreads();
    int hp = tid >> 2, o = tid & 3;
    __align__(16) __half hb[8];
#pragma unroll
    for (int j = 0; j < 8; j++) hb[j] = __float2half(s[o*8 + j][hp]);
    *(uint4*)&g_w1t[(size_t)e*H_*D_ + (size_t)(h0+hp)*D_ + d0 + o*8] = *(uint4*)hb;
}
__global__ void __launch_bounds__(128) k_tr2(const float* __restrict__ w) {
    __shared__ float s[32][33];
    int e = blockIdx.z, d0 = blockIdx.x*32, h0 = blockIdx.y*32;
    const float* S = w + (size_t)e * H_ * D_;
    int tid = threadIdx.x;
#pragma unroll
    for (int it = 0; it < 2; it++) {
        int hr = (tid >> 3) + it*16;
        int dc = (tid & 7) * 4;
        float4 v = *(const float4*)&S[(size_t)(h0+hr)*D_ + d0 + dc];
        s[hr][dc] = v.x; s[hr][dc+1] = v.y; s[hr][dc+2] = v.z; s[hr][dc+3] = v.w;
    }
    __syncthreads();
    int dp = tid >> 2, o = tid & 3;
    __align__(16) __half hb[8];
#pragma unroll
    for (int j = 0; j < 8; j++) hb[j] = __float2half(s[o*8 + j][dp]);
    *(uint4*)&g_w2t[(size_t)e*D_*H_ + (size_t)(d0+dp)*H_ + h0 + o*8] = *(uint4*)hb;
}

// ---------------- router: warp per token, block-aggregated atomics ----------------
#define RTOK 16
__global__ void __launch_bounds__(512) k_router(const float* __restrict__ x,
                                                const float* __restrict__ wr) {
    __shared__ float swr[8][1024];     // wr transposed
    __shared__ float sproxy[8];
    __shared__ float sz2;
    int tid = threadIdx.x;
    for (int d = tid; d < 1024; d += 512) {
        float4 a = *(const float4*)&wr[d*8];
        float4 b = *(const float4*)&wr[d*8 + 4];
        swr[0][d] = a.x; swr[1][d] = a.y; swr[2][d] = a.z; swr[3][d] = a.w;
        swr[4][d] = b.x; swr[5][d] = b.y; swr[6][d] = b.z; swr[7][d] = b.w;
    }
    if (tid < 8) sproxy[tid] = 0.f;
    if (tid == 8) sz2 = 0.f;
    __syncthreads();

    int warp = tid >> 5, lane = tid & 31;
    int t = blockIdx.x * RTOK + warp;
    int b = t / N_;
    const float* xr = x + (size_t)t * D_;
    __half* xtr = g_xh + (size_t)t * D_;

    float acc[8];
#pragma unroll
    for (int e = 0; e < 8; e++) acc[e] = 0.f;
#pragma unroll
    for (int i = 0; i < 8; i++) {
        int d = i*128 + lane*4;
        float4 xv = __ldg((const float4*)(xr + d));
        __align__(8) __half2 hh[2];
        hh[0] = __floats2half2_rn(xv.x, xv.y);
        hh[1] = __floats2half2_rn(xv.z, xv.w);
        *(uint2*)(xtr + d) = *(uint2*)hh;
#pragma unroll
        for (int e = 0; e < 8; e++) {
            float4 w = *(const float4*)&swr[e][d];
            acc[e] += xv.x*w.x + xv.y*w.y + xv.z*w.z + xv.w*w.w;
        }
    }
#pragma unroll
    for (int e = 0; e < 8; e++)
#pragma unroll
        for (int off = 16; off > 0; off >>= 1)
            acc[e] += __shfl_xor_sync(0xffffffffu, acc[e], off);

    if (lane == 0) {
        float maxl = acc[0]; int amax = 0;
#pragma unroll
        for (int e = 1; e < 8; e++) if (acc[e] > maxl) { maxl = acc[e]; amax = e; }
        float sum = 0.f, p[8];
#pragma unroll
        for (int e = 0; e < 8; e++) { p[e] = expf(acc[e] - maxl); sum += p[e]; }
        float inv = 1.f / sum;
        float z = maxl + logf(sum);
#pragma unroll
        for (int e = 0; e < 8; e++) atomicAdd(&sproxy[e], p[e] * inv);
        atomicAdd(&sz2, z * z);
        g_idx[t]  = amax;
        g_gate[t] = p[amax] * inv;
    }
    __syncthreads();
    if (tid < 8)  atomicAdd(&g_proxy[b*8 + tid], sproxy[tid]);
    if (tid == 8) atomicAdd(&g_z2, sz2);
}

// ---------------- capacity scan ----------------
__global__ void k_scan() {
    int be = blockIdx.x;
    int b = be / E_, e = be % E_;
    int lane = threadIdx.x;
    unsigned lt = (1u << lane) - 1u;
    int base = 0;
    for (int n0 = 0; n0 < N_; n0 += 256) {
        int v[8];
#pragma unroll
        for (int u = 0; u < 8; u++) v[u] = __ldg(&g_idx[b*N_ + n0 + u*32 + lane]);
#pragma unroll
        for (int u = 0; u < 8; u++) {
            int pred = (v[u] == e);
            unsigned bal = __ballot_sync(0xffffffffu, pred);
            if (pred) {
                int slot = base + __popc(bal & lt);
                if (slot < C_) g_s2t[be*C_ + slot] = n0 + u*32 + lane;
            }
            base += __popc(bal);
        }
    }
    if (lane == 0) g_cnt[be] = base;
}

// ---------------- scalar losses (parallel) ----------------
__global__ void k_final(float* __restrict__ out) {
    int i = threadIdx.x;   // 32 threads, one per (b,e)
    float v = ((float)g_cnt[i] / (float)N_) * (g_proxy[i] / (float)N_);
#pragma unroll
    for (int off = 16; off > 0; off >>= 1) v += __shfl_xor_sync(0xffffffffu, v, off);
    if (i == 0) {
        out[(size_t)BN_TOK * D_]     = v * (float)(E_*E_) / (float)B_;
        out[(size_t)BN_TOK * D_ + 1] = g_z2 / (float)BN_TOK;
    }
}

// ---------------- fp16 mma GEMM: BM=64 BN=128 BK=32, 4 warps (2x2), warp 32x64 ----------------
#define PA 40   // pitch in halves (80 bytes)

template<bool IS_G1>
__global__ void __launch_bounds__(128, 2) k_mma(const float* __restrict__ bias,
                                                float* __restrict__ outp)
{
    constexpr int KDIM  = IS_G1 ? D_ : H_;
    constexpr int ITERS = KDIM / 32;
    constexpr int AS_H = 64*PA, BS_H = 128*PA;

    __shared__ __align__(16) __half As[3*AS_H];
    __shared__ __align__(16) __half Bs[3*BS_H];
    __shared__ int tok[64];

    int be = blockIdx.z, b = be >> 3, e = be & 7;
    int m0 = blockIdx.y * 64, n0 = blockIdx.x * 128;
    int tid = threadIdx.x, lane = tid & 31, wid = tid >> 5;

    if (tid < 64) tok[tid] = g_s2t[be*C_ + m0 + tid];
    __syncthreads();

    int ar0 = tid >> 2, ar1 = ar0 + 32, akc = tid & 3;
    int br0 = tid >> 2, bkc = tid & 3;

    const __half* aS0; const __half* aS1; int az0, az1;
    if (IS_G1) {
        int t0 = tok[ar0], t1 = tok[ar1];
        aS0 = (t0 >= 0) ? g_xh + ((size_t)(b*N_ + t0) * D_ + akc*8) : g_xh;
        aS1 = (t1 >= 0) ? g_xh + ((size_t)(b*N_ + t1) * D_ + akc*8) : g_xh;
        az0 = (t0 >= 0) ? 16 : 0;  az1 = (t1 >= 0) ? 16 : 0;
    } else {
        aS0 = g_Yh + ((size_t)be*C_ + m0 + ar0) * H_ + akc*8;
        aS1 = g_Yh + ((size_t)be*C_ + m0 + ar1) * H_ + akc*8;
        az0 = 16; az1 = 16;
    }
    const __half* wt = IS_G1 ? g_w1t : g_w2t;
    const __half* wbase = wt + (size_t)e * (IS_G1 ? (size_t)H_*D_ : (size_t)D_*H_)
                        + (size_t)(n0 + br0) * KDIM + bkc*8;

    unsigned saA0 = (unsigned)__cvta_generic_to_shared(&As[ar0*PA + akc*8]);
    unsigned saA1 = (unsigned)__cvta_generic_to_shared(&As[ar1*PA + akc*8]);
    unsigned saB0 = (unsigned)__cvta_generic_to_shared(&Bs[br0*PA + bkc*8]);
    constexpr unsigned A_ST = AS_H*2, B_ST = BS_H*2;

    auto fill = [&](int st, int k0) {
        cp16(saA0 + st*A_ST, aS0 + k0, az0);
        cp16(saA1 + st*A_ST, aS1 + k0, az1);
#pragma unroll
        for (int j = 0; j < 4; j++)
            cp16(saB0 + st*B_ST + j*32*PA*2, wbase + (size_t)32*j*KDIM + k0, 16);
        cpcommit();
    };

    float acc[2][8][4];
#pragma unroll
    for (int i = 0; i < 2; i++)
#pragma unroll
        for (int j = 0; j < 8; j++)
#pragma unroll
            for (int k = 0; k < 4; k++) acc[i][j][k] = 0.f;

    fill(0, 0);
    fill(1, 32);

    int wm = wid & 1, wn = wid >> 1;
    int gq = lane >> 2, t4 = lane & 3;

    for (int it = 0; it < ITERS; ++it) {
        int cur = it % 3;
        cpwait<1>();
        __syncthreads();

        int nxt = it + 2;
        if (nxt < ITERS) fill(nxt % 3, nxt * 32);
        else cpcommit();

        const __half* Ac = &As[cur*AS_H];
        const __half* Bc = &Bs[cur*BS_H];
#pragma unroll
        for (int s = 0; s < 2; s++) {
            unsigned a[2][4], bf[8][2];
            int kh = s*16 + 2*t4;
#pragma unroll
            for (int mt = 0; mt < 2; mt++) {
                int rm = wm*32 + mt*16 + gq;
                a[mt][0] = *(const unsigned*)&Ac[rm*PA + kh];
                a[mt][1] = *(const unsigned*)&Ac[(rm+8)*PA + kh];
                a[mt][2] = *(const unsigned*)&Ac[rm*PA + kh + 8];
                a[mt][3] = *(const unsigned*)&Ac[(rm+8)*PA + kh + 8];
            }
#pragma unroll
            for (int nt = 0; nt < 8; nt++) {
                int nn = wn*64 + nt*8 + gq;
                bf[nt][0] = *(const unsigned*)&Bc[nn*PA + kh];
                bf[nt][1] = *(const unsigned*)&Bc[nn*PA + kh + 8];
            }
#pragma unroll
            for (int mt = 0; mt < 2; mt++)
#pragma unroll
                for (int nt = 0; nt < 8; nt++) mma16(acc[mt][nt], a[mt], bf[nt]);
        }
    }

    // ---------------- epilogue ----------------
    if (IS_G1) {
#pragma unroll
        for (int mt = 0; mt < 2; mt++) {
            int r1 = m0 + wm*32 + mt*16 + gq, r2 = r1 + 8;
#pragma unroll
            for (int nt = 0; nt < 8; nt++) {
                int gn = n0 + wn*64 + nt*8 + 2*t4;
                float2 bv = *(const float2*)&bias[(size_t)e*H_ + gn];
                __half2 v1, v2;
                v1.x = __float2half(gelu_tanh(acc[mt][nt][0] + bv.x));
                v1.y = __float2half(gelu_tanh(acc[mt][nt][1] + bv.y));
                v2.x = __float2half(gelu_tanh(acc[mt][nt][2] + bv.x));
                v2.y = __float2half(gelu_tanh(acc[mt][nt][3] + bv.y));
                *(__half2*)&g_Yh[((size_t)be*C_ + r1)*H_ + gn] = v1;
                *(__half2*)&g_Yh[((size_t)be*C_ + r2)*H_ + gn] = v2;
            }
        }
    } else {
#pragma unroll
        for (int mt = 0; mt < 2; mt++) {
            int r = wm*32 + mt*16 + gq;
            int tk1 = tok[r], tk2 = tok[r + 8];
            float gv1 = (tk1 >= 0) ? g_gate[b*N_ + tk1] : 0.f;
            float gv2 = (tk2 >= 0) ? g_gate[b*N_ + tk2] : 0.f;
#pragma unroll
            for (int nt = 0; nt < 8; nt++) {
                int gn = n0 + wn*64 + nt*8 + 2*t4;
                float2 bv = *(const float2*)&bias[(size_t)e*D_ + gn];
                if (tk1 >= 0) {
                    float2 v = { gv1*(acc[mt][nt][0] + bv.x), gv1*(acc[mt][nt][1] + bv.y) };
                    *(float2*)&outp[((size_t)(b*N_ + tk1))*D_ + gn] = v;
                }
                if (tk2 >= 0) {
                    float2 v = { gv2*(acc[mt][nt][2] + bv.x), gv2*(acc[mt][nt][3] + bv.y) };
                    *(float2*)&outp[((size_t)(b*N_ + tk2))*D_ + gn] = v;
                }
            }
        }
    }
}

// ---------------- launch ----------------
extern "C" void kernel_launch(void* const* d_in, const int* in_sizes, int n_in,
                              void* d_out, int out_size) {
    const float* x  = (const float*)d_in[0];
    const float* wr = (const float*)d_in[1];
    const float* w1 = (const float*)d_in[2];
    const float* b1 = (const float*)d_in[3];
    const float* w2 = (const float*)d_in[4];
    const float* b2 = (const float*)d_in[5];
    float* out = (float*)d_out;

    cudaMemsetAsync(out, 0, (size_t)out_size * sizeof(float), 0);
    k_init<<<(B_*E_*C_ + 255) / 256, 256>>>();
    k_tr1<<<dim3(H_/32, D_/32, E_), 128>>>(w1);
    k_tr2<<<dim3(D_/32, H_/32, E_), 128>>>(w2);
    k_router<<<BN_TOK/RTOK, 512>>>(x, wr);
    k_scan<<<B_*E_, 32>>>();
    k_final<<<1, 32>>>(out);
    k_mma<true ><<<dim3(H_/128, C_/64, B_*E_), 128>>>(b1, nullptr);
    k_mma<false><<<dim3(D_/128, C_/64, B_*E_), 128>>>(b2, out);
}

// round 7
// speedup vs baseline: 6.7536x; 1.1003x over previous
#include <cuda_runtime.h>
#include <cuda_fp16.h>
#include <math.h>
#include <stdint.h>

#define B_  4
#define N_  2048
#define D_  1024
#define E_  8
#define H_  4096
#define C_  320
#define BN_TOK (B_*N_)

// -------- scratch (device globals: allocation-free) --------
__device__ __half g_Yh[(size_t)B_*E_*C_*H_];   // expert hidden, fp16
__device__ __half g_xh[(size_t)BN_TOK*D_];     // x in fp16
__device__ __half g_w1t[(size_t)E_*H_*D_];     // w1 transposed: [E][H][D] fp16 (K-major)
__device__ __half g_w2t[(size_t)E_*D_*H_];     // w2 transposed: [E][D][H] fp16 (K-major)
__device__ int    g_s2t[B_*E_*C_];
__device__ int    g_cnt[B_*E_];
__device__ float  g_proxy[B_*E_];
__device__ float  g_gate[BN_TOK];
__device__ int    g_idx[BN_TOK];
__device__ float  g_z2;

// ---------------- helpers ----------------
__device__ __forceinline__ void mma16(float c[4], const unsigned a[4], const unsigned b[2]) {
    asm volatile("mma.sync.aligned.m16n8k16.row.col.f32.f16.f16.f32 "
                 "{%0,%1,%2,%3},{%4,%5,%6,%7},{%8,%9},{%0,%1,%2,%3};"
                 : "+f"(c[0]), "+f"(c[1]), "+f"(c[2]), "+f"(c[3])
                 : "r"(a[0]), "r"(a[1]), "r"(a[2]), "r"(a[3]), "r"(b[0]), "r"(b[1]));
}
__device__ __forceinline__ void cp16(unsigned saddr, const void* g, int sz) {
    asm volatile("cp.async.cg.shared.global [%0], [%1], 16, %2;"
                 :: "r"(saddr), "l"(g), "r"(sz));
}
__device__ __forceinline__ void cpcommit() { asm volatile("cp.async.commit_group;"); }
template<int n> __device__ __forceinline__ void cpwait() {
    asm volatile("cp.async.wait_group %0;" :: "n"(n));
}
__device__ __forceinline__ float gelu_tanh(float v) {
    float v3 = v * v * v;
    return 0.5f * v * (1.f + tanhf(0.7978845608028654f * (v + 0.044715f * v3)));
}

// ---------------- init ----------------
__global__ void k_init() {
    int i = blockIdx.x * blockDim.x + threadIdx.x;
    if (i < B_*E_*C_) g_s2t[i] = -1;
    if (i < B_*E_)    g_proxy[i] = 0.f;
    if (i == 0)       g_z2 = 0.f;
}

// ---------------- weight transposes -> fp16 K-major (vectorized) ----------------
__global__ void __launch_bounds__(128) k_tr1(const float* __restrict__ w) {
    __shared__ float s[32][33];
    int e = blockIdx.z, h0 = blockIdx.x*32, d0 = blockIdx.y*32;
    const float* S = w + (size_t)e * D_ * H_;
    int tid = threadIdx.x;
#pragma unroll
    for (int it = 0; it < 2; it++) {
        int dr = (tid >> 3) + it*16;
        int hc = (tid & 7) * 4;
        float4 v = *(const float4*)&S[(size_t)(d0+dr)*H_ + h0 + hc];
        s[dr][hc] = v.x; s[dr][hc+1] = v.y; s[dr][hc+2] = v.z; s[dr][hc+3] = v.w;
    }
    __syncthreads();
    int hp = tid >> 2, o = tid & 3;
    __align__(16) __half hb[8];
#pragma unroll
    for (int j = 0; j < 8; j++) hb[j] = __float2half(s[o*8 + j][hp]);
    *(uint4*)&g_w1t[(size_t)e*H_*D_ + (size_t)(h0+hp)*D_ + d0 + o*8] = *(uint4*)hb;
}
__global__ void __launch_bounds__(128) k_tr2(const float* __restrict__ w) {
    __shared__ float s[32][33];
    int e = blockIdx.z, d0 = blockIdx.x*32, h0 = blockIdx.y*32;
    const float* S = w + (size_t)e * H_ * D_;
    int tid = threadIdx.x;
#pragma unroll
    for (int it = 0; it < 2; it++) {
        int hr = (tid >> 3) + it*16;
        int dc = (tid & 7) * 4;
        float4 v = *(const float4*)&S[(size_t)(h0+hr)*D_ + d0 + dc];
        s[hr][dc] = v.x; s[hr][dc+1] = v.y; s[hr][dc+2] = v.z; s[hr][dc+3] = v.w;
    }
    __syncthreads();
    int dp = tid >> 2, o = tid & 3;
    __align__(16) __half hb[8];
#pragma unroll
    for (int j = 0; j < 8; j++) hb[j] = __float2half(s[o*8 + j][dp]);
    *(uint4*)&g_w2t[(size_t)e*D_*H_ + (size_t)(d0+dp)*H_ + h0 + o*8] = *(uint4*)hb;
}

// ---------------- router: warp per token, block-aggregated atomics ----------------
#define RTOK 16
__global__ void __launch_bounds__(512) k_router(const float* __restrict__ x,
                                                const float* __restrict__ wr) {
    __shared__ float swr[8][1024];
    __shared__ float sproxy[8];
    __shared__ float sz2;
    int tid = threadIdx.x;
    for (int d = tid; d < 1024; d += 512) {
        float4 a = *(const float4*)&wr[d*8];
        float4 b = *(const float4*)&wr[d*8 + 4];
        swr[0][d] = a.x; swr[1][d] = a.y; swr[2][d] = a.z; swr[3][d] = a.w;
        swr[4][d] = b.x; swr[5][d] = b.y; swr[6][d] = b.z; swr[7][d] = b.w;
    }
    if (tid < 8) sproxy[tid] = 0.f;
    if (tid == 8) sz2 = 0.f;
    __syncthreads();

    int warp = tid >> 5, lane = tid & 31;
    int t = blockIdx.x * RTOK + warp;
    int b = t / N_;
    const float* xr = x + (size_t)t * D_;
    __half* xtr = g_xh + (size_t)t * D_;

    float acc[8];
#pragma unroll
    for (int e = 0; e < 8; e++) acc[e] = 0.f;
#pragma unroll
    for (int i = 0; i < 8; i++) {
        int d = i*128 + lane*4;
        float4 xv = __ldg((const float4*)(xr + d));
        __align__(8) __half2 hh[2];
        hh[0] = __floats2half2_rn(xv.x, xv.y);
        hh[1] = __floats2half2_rn(xv.z, xv.w);
        *(uint2*)(xtr + d) = *(uint2*)hh;
#pragma unroll
        for (int e = 0; e < 8; e++) {
            float4 w = *(const float4*)&swr[e][d];
            acc[e] += xv.x*w.x + xv.y*w.y + xv.z*w.z + xv.w*w.w;
        }
    }
#pragma unroll
    for (int e = 0; e < 8; e++)
#pragma unroll
        for (int off = 16; off > 0; off >>= 1)
            acc[e] += __shfl_xor_sync(0xffffffffu, acc[e], off);

    if (lane == 0) {
        float maxl = acc[0]; int amax = 0;
#pragma unroll
        for (int e = 1; e < 8; e++) if (acc[e] > maxl) { maxl = acc[e]; amax = e; }
        float sum = 0.f, p[8];
#pragma unroll
        for (int e = 0; e < 8; e++) { p[e] = expf(acc[e] - maxl); sum += p[e]; }
        float inv = 1.f / sum;
        float z = maxl + logf(sum);
#pragma unroll
        for (int e = 0; e < 8; e++) atomicAdd(&sproxy[e], p[e] * inv);
        atomicAdd(&sz2, z * z);
        g_idx[t]  = amax;
        g_gate[t] = p[amax] * inv;
    }
    __syncthreads();
    if (tid < 8)  atomicAdd(&g_proxy[b*8 + tid], sproxy[tid]);
    if (tid == 8) atomicAdd(&g_z2, sz2);
}

// ---------------- capacity scan ----------------
__global__ void k_scan() {
    int be = blockIdx.x;
    int b = be / E_, e = be % E_;
    int lane = threadIdx.x;
    unsigned lt = (1u << lane) - 1u;
    int base = 0;
    for (int n0 = 0; n0 < N_; n0 += 256) {
        int v[8];
#pragma unroll
        for (int u = 0; u < 8; u++) v[u] = __ldg(&g_idx[b*N_ + n0 + u*32 + lane]);
#pragma unroll
        for (int u = 0; u < 8; u++) {
            int pred = (v[u] == e);
            unsigned bal = __ballot_sync(0xffffffffu, pred);
            if (pred) {
                int slot = base + __popc(bal & lt);
                if (slot < C_) g_s2t[be*C_ + slot] = n0 + u*32 + lane;
            }
            base += __popc(bal);
        }
    }
    if (lane == 0) g_cnt[be] = base;
}

// ---------------- scalar losses (parallel) ----------------
__global__ void k_final(float* __restrict__ out) {
    int i = threadIdx.x;
    float v = ((float)g_cnt[i] / (float)N_) * (g_proxy[i] / (float)N_);
#pragma unroll
    for (int off = 16; off > 0; off >>= 1) v += __shfl_xor_sync(0xffffffffu, v, off);
    if (i == 0) {
        out[(size_t)BN_TOK * D_]     = v * (float)(E_*E_) / (float)B_;
        out[(size_t)BN_TOK * D_ + 1] = g_z2 / (float)BN_TOK;
    }
}

// ---------------- fp16 mma GEMM: BM=64 BN=128 BK=32, 4 warps (2x2), warp 32x64 ----------------
#define PA 40   // pitch in halves (80 bytes)

template<bool IS_G1, int OCC>
__global__ void __launch_bounds__(128, OCC) k_mma(const float* __restrict__ bias,
                                                  float* __restrict__ outp)
{
    constexpr int KDIM  = IS_G1 ? D_ : H_;
    constexpr int ITERS = KDIM / 32;
    constexpr int AS_H = 64*PA, BS_H = 128*PA;

    __shared__ __align__(16) __half As[3*AS_H];
    __shared__ __align__(16) __half Bs[3*BS_H];
    __shared__ int tok[64];

    int be = blockIdx.z, b = be >> 3, e = be & 7;
    int m0 = blockIdx.y * 64, n0 = blockIdx.x * 128;
    int tid = threadIdx.x, lane = tid & 31, wid = tid >> 5;

    // skip fully-empty capacity tiles (no token routed into [m0, m0+64))
    if (__ldg(&g_cnt[be]) <= m0) return;

    if (tid < 64) tok[tid] = g_s2t[be*C_ + m0 + tid];
    __syncthreads();

    int ar0 = tid >> 2, ar1 = ar0 + 32, akc = tid & 3;
    int br0 = tid >> 2, bkc = tid & 3;

    const __half* aS0; const __half* aS1; int az0, az1;
    if (IS_G1) {
        int t0 = tok[ar0], t1 = tok[ar1];
        aS0 = (t0 >= 0) ? g_xh + ((size_t)(b*N_ + t0) * D_ + akc*8) : g_xh;
        aS1 = (t1 >= 0) ? g_xh + ((size_t)(b*N_ + t1) * D_ + akc*8) : g_xh;
        az0 = (t0 >= 0) ? 16 : 0;  az1 = (t1 >= 0) ? 16 : 0;
    } else {
        // gate on slot occupancy: empty slots read zeros (their g_Yh rows may be stale)
        int t0 = tok[ar0], t1 = tok[ar1];
        aS0 = g_Yh + ((size_t)be*C_ + m0 + ar0) * H_ + akc*8;
        aS1 = g_Yh + ((size_t)be*C_ + m0 + ar1) * H_ + akc*8;
        az0 = (t0 >= 0) ? 16 : 0;  az1 = (t1 >= 0) ? 16 : 0;
    }
    const __half* wt = IS_G1 ? g_w1t : g_w2t;
    const __half* wbase = wt + (size_t)e * (IS_G1 ? (size_t)H_*D_ : (size_t)D_*H_)
                        + (size_t)(n0 + br0) * KDIM + bkc*8;

    unsigned saA0 = (unsigned)__cvta_generic_to_shared(&As[ar0*PA + akc*8]);
    unsigned saA1 = (unsigned)__cvta_generic_to_shared(&As[ar1*PA + akc*8]);
    unsigned saB0 = (unsigned)__cvta_generic_to_shared(&Bs[br0*PA + bkc*8]);
    constexpr unsigned A_ST = AS_H*2, B_ST = BS_H*2;

    auto fill = [&](int st, int k0) {
        cp16(saA0 + st*A_ST, aS0 + k0, az0);
        cp16(saA1 + st*A_ST, aS1 + k0, az1);
#pragma unroll
        for (int j = 0; j < 4; j++)
            cp16(saB0 + st*B_ST + j*32*PA*2, wbase + (size_t)32*j*KDIM + k0, 16);
        cpcommit();
    };

    float acc[2][8][4];
#pragma unroll
    for (int i = 0; i < 2; i++)
#pragma unroll
        for (int j = 0; j < 8; j++)
#pragma unroll
            for (int k = 0; k < 4; k++) acc[i][j][k] = 0.f;

    fill(0, 0);
    fill(1, 32);

    int wm = wid & 1, wn = wid >> 1;
    int gq = lane >> 2, t4 = lane & 3;

    for (int it = 0; it < ITERS; ++it) {
        int cur = it % 3;
        cpwait<1>();
        __syncthreads();

        int nxt = it + 2;
        if (nxt < ITERS) fill(nxt % 3, nxt * 32);
        else cpcommit();

        const __half* Ac = &As[cur*AS_H];
        const __half* Bc = &Bs[cur*BS_H];
#pragma unroll
        for (int s = 0; s < 2; s++) {
            unsigned a[2][4], bf[8][2];
            int kh = s*16 + 2*t4;
#pragma unroll
            for (int mt = 0; mt < 2; mt++) {
                int rm = wm*32 + mt*16 + gq;
                a[mt][0] = *(const unsigned*)&Ac[rm*PA + kh];
                a[mt][1] = *(const unsigned*)&Ac[(rm+8)*PA + kh];
                a[mt][2] = *(const unsigned*)&Ac[rm*PA + kh + 8];
                a[mt][3] = *(const unsigned*)&Ac[(rm+8)*PA + kh + 8];
            }
#pragma unroll
            for (int nt = 0; nt < 8; nt++) {
                int nn = wn*64 + nt*8 + gq;
                bf[nt][0] = *(const unsigned*)&Bc[nn*PA + kh];
                bf[nt][1] = *(const unsigned*)&Bc[nn*PA + kh + 8];
            }
#pragma unroll
            for (int mt = 0; mt < 2; mt++)
#pragma unroll
                for (int nt = 0; nt < 8; nt++) mma16(acc[mt][nt], a[mt], bf[nt]);
        }
    }

    // ---------------- epilogue ----------------
    if (IS_G1) {
#pragma unroll
        for (int mt = 0; mt < 2; mt++) {
            int r1 = m0 + wm*32 + mt*16 + gq, r2 = r1 + 8;
#pragma unroll
            for (int nt = 0; nt < 8; nt++) {
                int gn = n0 + wn*64 + nt*8 + 2*t4;
                float2 bv = *(const float2*)&bias[(size_t)e*H_ + gn];
                __half2 v1, v2;
                v1.x = __float2half(gelu_tanh(acc[mt][nt][0] + bv.x));
                v1.y = __float2half(gelu_tanh(acc[mt][nt][1] + bv.y));
                v2.x = __float2half(gelu_tanh(acc[mt][nt][2] + bv.x));
                v2.y = __float2half(gelu_tanh(acc[mt][nt][3] + bv.y));
                *(__half2*)&g_Yh[((size_t)be*C_ + r1)*H_ + gn] = v1;
                *(__half2*)&g_Yh[((size_t)be*C_ + r2)*H_ + gn] = v2;
            }
        }
    } else {
#pragma unroll
        for (int mt = 0; mt < 2; mt++) {
            int r = wm*32 + mt*16 + gq;
            int tk1 = tok[r], tk2 = tok[r + 8];
            float gv1 = (tk1 >= 0) ? g_gate[b*N_ + tk1] : 0.f;
            float gv2 = (tk2 >= 0) ? g_gate[b*N_ + tk2] : 0.f;
#pragma unroll
            for (int nt = 0; nt < 8; nt++) {
                int gn = n0 + wn*64 + nt*8 + 2*t4;
                float2 bv = *(const float2*)&bias[(size_t)e*D_ + gn];
                if (tk1 >= 0) {
                    float2 v = { gv1*(acc[mt][nt][0] + bv.x), gv1*(acc[mt][nt][1] + bv.y) };
                    *(float2*)&outp[((size_t)(b*N_ + tk1))*D_ + gn] = v;
                }
                if (tk2 >= 0) {
                    float2 v = { gv2*(acc[mt][nt][2] + bv.x), gv2*(acc[mt][nt][3] + bv.y) };
                    *(float2*)&outp[((size_t)(b*N_ + tk2))*D_ + gn] = v;
                }
            }
        }
    }
}

// ---------------- launch ----------------
extern "C" void kernel_launch(void* const* d_in, const int* in_sizes, int n_in,
                              void* d_out, int out_size) {
    const float* x  = (const float*)d_in[0];
    const float* wr = (const float*)d_in[1];
    const float* w1 = (const float*)d_in[2];
    const float* b1 = (const float*)d_in[3];
    const float* w2 = (const float*)d_in[4];
    const float* b2 = (const float*)d_in[5];
    float* out = (float*)d_out;

    cudaMemsetAsync(out, 0, (size_t)out_size * sizeof(float), 0);
    k_init<<<(B_*E_*C_ + 255) / 256, 256>>>();
    k_tr1<<<dim3(H_/32, D_/32, E_), 128>>>(w1);
    k_tr2<<<dim3(D_/32, H_/32, E_), 128>>>(w2);
    k_router<<<BN_TOK/RTOK, 512>>>(x, wr);
    k_scan<<<B_*E_, 32>>>();
    k_final<<<1, 32>>>(out);
    k_mma<true,  2><<<dim3(H_/128, C_/64, B_*E_), 128>>>(b1, nullptr);
    k_mma<false, 3><<<dim3(D_/128, C_/64, B_*E_), 128>>>(b2, out);
}